// round 14
// baseline (speedup 1.0000x reference)
#include <cuda_runtime.h>
#include <cuda_pipeline.h>
#include <math.h>

#define NFFT   512
#define NFREQ  257
#define HOP    64
#define BATCH  32
#define TLEN   256000
#define TF     4001
#define TF2    4096                 // padded band row stride
#define TB2    4096                 // padded t rows per batch (mag)
#define FP     268                  // mag f-row stride (floats), 16B-aligned
#define NB     40
#define NFRAMES (BATCH*TF)
#define NTB     251                 // 16-frame tiles per batch
#define FEAT_ELEMS ((size_t)BATCH*NB*TF)

// segmented speculative scan params (aligned grid)
#define SEGL   256
#define WARM   192                  // contraction (1-fall)^192 ~ 9e-5
#define TC     8                    // t per chunk
#define WCHK   (WARM/TC)            // 24 warm chunks
#define SCHK   (SEGL/TC)            // 32 write chunks
#define NBT    320                  // noise_band threads = NB*TC tasks

// ---------------- scratch (no cudaMalloc allowed; zero-initialized) ----------
__device__ float g_tw_re[512];
__device__ float g_tw_im[512];
__device__ float g_mag [(size_t)BATCH * TB2 * FP];   // (b,t,f) natural, padded
__device__ float g_band[(size_t)BATCH * NB * TF2];   // (b,n,t) padded
__device__ int   g_lo [NB];
__device__ int   g_off[NB + 1];
__device__ float g_w  [768];        // CSR weights, nnz <= 514

// ---------------- init: twiddles + CSR of triangular fb ----------------
__global__ void init_twiddles() {
    int k = threadIdx.x;            // 512 threads
    double ang = -2.0 * M_PI * (double)k / (double)NFFT;
    g_tw_re[k] = (float)cos(ang);
    g_tw_im[k] = (float)sin(ang);
}

// fb rows are contiguous nonzero runs [lo, hi); build CSR (lo, off, w).
__global__ void init_csr(const float* __restrict__ fb) {
    __shared__ int s_len[NB];
    int n = threadIdx.x;            // 64 threads
    if (n < NB) {
        int lo = NFREQ, hi = 0;
        for (int f = 0; f < NFREQ; ++f) {
            if (fb[n * NFREQ + f] != 0.0f) { if (f < lo) lo = f; hi = f + 1; }
        }
        if (hi <= lo) { lo = 0; hi = 0; }
        g_lo[n] = lo;
        s_len[n] = hi - lo;
    }
    __syncthreads();
    if (n == 0) {
        int off = 0;
        for (int i = 0; i < NB; ++i) { g_off[i] = off; off += s_len[i]; }
        g_off[NB] = off;
    }
    __syncthreads();
    if (n < NB) {
        int o = g_off[n], lo = g_lo[n], len = s_len[n];
        for (int i = 0; i < len; ++i) g_w[o + i] = fb[n * NFREQ + lo + i];
    }
}

// ---------------- complex helpers ----------------
__device__ __forceinline__ float2 cadd(float2 a, float2 b) { return make_float2(a.x+b.x, a.y+b.y); }
__device__ __forceinline__ float2 csub(float2 a, float2 b) { return make_float2(a.x-b.x, a.y-b.y); }
__device__ __forceinline__ float2 cmul(float2 a, float2 w) {
    return make_float2(fmaf(a.x, w.x, -a.y*w.y), fmaf(a.x, w.y, a.y*w.x));
}

// 8-point DFT
__device__ __forceinline__ void dft8(const float2* v, float2* y) {
    float2 e0s = cadd(v[0], v[4]), e0d = csub(v[0], v[4]);
    float2 e1s = cadd(v[2], v[6]), e1d = csub(v[2], v[6]);
    float2 o0s = cadd(v[1], v[5]), o0d = csub(v[1], v[5]);
    float2 o1s = cadd(v[3], v[7]), o1d = csub(v[3], v[7]);
    float2 E0 = cadd(e0s, e1s);
    float2 E2 = csub(e0s, e1s);
    float2 E1 = make_float2(e0d.x + e1d.y, e0d.y - e1d.x);
    float2 E3 = make_float2(e0d.x - e1d.y, e0d.y + e1d.x);
    float2 O0 = cadd(o0s, o1s);
    float2 O2 = csub(o0s, o1s);
    float2 O1 = make_float2(o0d.x + o1d.y, o0d.y - o1d.x);
    float2 O3 = make_float2(o0d.x - o1d.y, o0d.y + o1d.x);
    const float C = 0.70710678118654752440f;
    float2 t1 = make_float2(C*(O1.x + O1.y), C*(O1.y - O1.x));
    float2 t2 = make_float2(O2.y, -O2.x);
    float2 t3 = make_float2(C*(O3.y - O3.x), -C*(O3.x + O3.y));
    y[0] = cadd(E0, O0);  y[4] = csub(E0, O0);
    y[1] = cadd(E1, t1);  y[5] = csub(E1, t1);
    y[2] = cadd(E2, t2);  y[6] = csub(E2, t2);
    y[3] = cadd(E3, t3);  y[7] = csub(E3, t3);
}

// ---------------- K1: STFT magnitude -> natural (b,t,f) rows ----------------
__global__ void __launch_bounds__(256)
stft16_kernel(const float* __restrict__ x, const float* __restrict__ win) {
    __shared__ float buf_re[4][576], buf_im[4][576];
    __shared__ float magt[16][258];
    __shared__ float2 s_tw[512];

    int tid = threadIdx.x;
    int b  = blockIdx.x / NTB;
    int tb = blockIdx.x - b * NTB;
    int t0 = tb * 16;
    const float* xb = x + (size_t)b * TLEN;

    for (int i = tid; i < 512; i += 256)
        s_tw[i] = make_float2(g_tw_re[i], g_tw_im[i]);
    __syncthreads();

    int tile = tid >> 6;
    int j    = tid & 63;
    int mB = j >> 3, jp = j & 7;
    int mC = j & 7,  m2C = j >> 3;

    for (int half = 0; half < 2; ++half) {
        int pl  = half * 4 + tile;            // pair-local 0..7
        int tA = t0 + 2 * pl, tB = tA + 1;    // frame times

        float2 a[8], y[8];
        #pragma unroll
        for (int l = 0; l < 8; ++l) {
            int n = j + 64 * l;
            float w = win[n];
            int i0 = tA * HOP + n - 256;
            if (i0 < 0) i0 = -i0; else if (i0 >= TLEN) i0 = 2 * TLEN - 2 - i0;
            int i1 = tB * HOP + n - 256;
            if (i1 < 0) i1 = -i1; else if (i1 >= TLEN) i1 = 2 * TLEN - 2 - i1;
            a[l] = make_float2(xb[i0] * w, xb[i1] * w);
        }

        dft8(a, y);
        #pragma unroll
        for (int m = 0; m < 8; ++m) {
            float2 c = (m == 0) ? y[0] : cmul(y[m], s_tw[j * m]);
            int idx = m * 64 + (j ^ (m << 3));
            buf_re[tile][idx] = c.x;
            buf_im[tile][idx] = c.y;
        }
        __syncthreads();

        #pragma unroll
        for (int l2 = 0; l2 < 8; ++l2) {
            int src = jp + 8 * l2;
            int idx = mB * 64 + (src ^ (mB << 3));
            a[l2] = make_float2(buf_re[tile][idx], buf_im[tile][idx]);
        }
        __syncthreads();
        dft8(a, y);
        #pragma unroll
        for (int m2 = 0; m2 < 8; ++m2) {
            float2 e = (m2 == 0) ? y[0] : cmul(y[m2], s_tw[8 * jp * m2]);
            int idx = m2 * 72 + mB * 9 + jp;
            buf_re[tile][idx] = e.x;
            buf_im[tile][idx] = e.y;
        }
        __syncthreads();

        #pragma unroll
        for (int q = 0; q < 8; ++q) {
            int idx = m2C * 72 + mC * 9 + q;
            a[q] = make_float2(buf_re[tile][idx], buf_im[tile][idx]);
        }
        __syncthreads();
        dft8(a, y);
        #pragma unroll
        for (int k2 = 0; k2 < 8; ++k2) {
            int k = 64 * k2 + j;
            buf_re[tile][k] = y[k2].x;
            buf_im[tile][k] = y[k2].y;
        }
        __syncthreads();

        int jlA = 2 * pl, jlB = jlA + 1;
        #pragma unroll
        for (int q = 0; q < 4; ++q) {
            int k  = j + 64 * q;
            int k2 = (NFFT - k) & (NFFT - 1);
            float xr = buf_re[tile][k],  xi = buf_im[tile][k];
            float yr = buf_re[tile][k2], yi = buf_im[tile][k2];
            float ar = 0.5f * (xr + yr);
            float ai = 0.5f * (xi - yi);
            float br = 0.5f * (xi + yi);
            float bi = 0.5f * (yr - xr);
            magt[jlA][k] = sqrtf(ar * ar + ai * ai);
            magt[jlB][k] = sqrtf(br * br + bi * bi);
        }
        if (j == 0) {
            float xr = buf_re[tile][256], xi = buf_im[tile][256];
            magt[jlA][256] = fabsf(xr);
            magt[jlB][256] = fabsf(xi);
        }
        __syncthreads();
    }

    // natural-row write-out: 16 coalesced 1028B rows
    for (int fr = 0; fr < 16; ++fr) {
        int t = t0 + fr;
        if (t < TF) {
            float* dst = g_mag + ((size_t)b * TB2 + t) * FP;
            for (int f = tid; f < NFREQ; f += 256)
                dst[f] = magt[fr][f];
        }
    }
}

// ---------------- K2: FUSED noise scan + VNR + band reduction ----------------
// Block = (b, segment s): 320 threads. Scan phase: thread=f over all 257
// chains. Band phase: exactly one task per thread (40 bands x 8 t), with a
// width-balanced band permutation so every warp mixes narrow+wide triangles.
__global__ void __launch_bounds__(NBT)
noise_band_kernel(const float* __restrict__ raw_rise,
                  const float* __restrict__ raw_fall,
                  const float* __restrict__ noise_scale_p,
                  float* __restrict__ out) {
    __shared__ __align__(16) float mtile[2][TC * FP];  // 17.2 KB
    __shared__ __align__(16) float vtile[TC * FP];     //  8.6 KB
    __shared__ float s_w[768];

    int tid = threadIdx.x;            // 320 = 10 warps
    int b = blockIdx.x >> 4;
    int s = blockIdx.x & 15;

    for (int i = tid; i < 768; i += NBT) s_w[i] = g_w[i];

    // static task assignment: group g -> band (balanced narrow/wide pairing)
    int gtask = tid >> 3;             // 0..39
    int tl    = tid & 7;              // t within chunk
    int nband = (gtask & 1) ? (NB - 1 - (gtask >> 1)) : (gtask >> 1);
    int o0  = g_off[nband];
    int len = g_off[nband + 1] - o0;
    int lo  = g_lo[nband];

    float rise  = 1.0f / (1.0f + expf(-raw_rise[0]));
    float fall  = 1.0f / (1.0f + expf(-raw_fall[0]));
    float scale = fabsf(noise_scale_p[0]);
    float* out_vnr = out + FEAT_ELEMS;

    int f = tid;
    bool act = (f < NFREQ);
    size_t magb = (size_t)b * TB2;

    // floor = 0.5 * max(min over t<20, 1e-5); coalesced rows
    float mn = 3.4e38f;
    if (act) {
        #pragma unroll 4
        for (int t = 0; t < 20; ++t)
            mn = fminf(mn, g_mag[(magb + t) * FP + f]);
    }
    mn = fmaxf(mn, 1e-5f);
    float floorv = 0.5f * mn;
    float nf = mn;                    // exact init (s==0)

    int t0 = s * SEGL;
    int tstart = s ? (t0 - WARM) : 0;
    int wch = s ? WCHK : 0;
    int nch = wch + SCHK;

    // per-task hoisted pointers (band phase)
    const float* vbase = vtile + tl * FP + lo;
    size_t bandrow = ((size_t)b * NB + nband) * TF2;
    size_t vnrrow  = ((size_t)b * NB + nband) * TF;

    // prime chunk 0
    {
        const float* src = g_mag + (magb + tstart) * FP;
        for (int i = tid; i < TC * 67; i += NBT) {
            int row = i / 67, c = i - row * 67;
            __pipeline_memcpy_async(&mtile[0][row * FP + c * 4],
                                    src + (size_t)row * FP + c * 4, 16);
        }
        __pipeline_commit();
    }

    for (int ch = 0; ch < nch; ++ch) {
        int cur = ch & 1;
        __pipeline_wait_prior(0);
        __syncthreads();              // mtile[cur] ready; prev phase2 done

        if (ch + 1 < nch) {           // prefetch next chunk
            const float* src = g_mag + (magb + tstart + (ch + 1) * TC) * FP;
            float* dst = mtile[cur ^ 1];
            for (int i = tid; i < TC * 67; i += NBT) {
                int row = i / 67, c = i - row * 67;
                __pipeline_memcpy_async(&dst[row * FP + c * 4],
                                        src + (size_t)row * FP + c * 4, 16);
            }
            __pipeline_commit();
        }

        bool wr = (ch >= wch);
        if (act) {
            if (ch == 0 && s) nf = fmaxf(mtile[cur][f], floorv);  // spec init
            #pragma unroll
            for (int i = 0; i < TC; ++i) {
                float m = mtile[cur][i * FP + f];
                float d = m - nf;
                float a = (d > 0.0f) ? rise : fall;
                nf = fmaxf(fmaf(a, d, nf), floorv);
                if (wr) vtile[i * FP + f] = __fdividef(m, fmaf(scale, nf, 1e-8f));
            }
        }

        if (wr) {
            __syncthreads();          // vtile ready
            int tg = tstart + ch * TC + tl;
            if (tg < TF) {
                const float* mp = mtile[cur] + tl * FP + lo;
                const float* vp = vbase;
                const float* wp = s_w + o0;
                float sb = 0.0f, sv = 0.0f;
                for (int o = 0; o < len; ++o) {
                    float w = wp[o];
                    sb = fmaf(w, mp[o], sb);
                    sv = fmaf(w, vp[o], sv);
                }
                g_band[bandrow + tg] = sb;
                out_vnr[vnrrow + tg] = tanhf(sv * 0.1f);
            }
        }
    }
}

// ---------------- K3: kurtosis gate + standardize (512 threads) --------------
__device__ __forceinline__ float block_reduce_sum512(float v, float* red) {
    #pragma unroll
    for (int o = 16; o; o >>= 1) v += __shfl_xor_sync(0xffffffffu, v, o);
    int w = threadIdx.x >> 5, l = threadIdx.x & 31;
    __syncthreads();
    if (l == 0) red[w] = v;
    __syncthreads();
    float r = (l < 16) ? red[l] : 0.0f;
    if (w == 0) {
        #pragma unroll
        for (int o = 8; o; o >>= 1) r += __shfl_xor_sync(0xffffffffu, r, o);
        if (l == 0) red[0] = r;
    }
    __syncthreads();
    return red[0];
}

__global__ void __launch_bounds__(512)
gate_kernel(const float* __restrict__ gw_p,
            const float* __restrict__ gb_p,
            const float* __restrict__ gf_p,
            float* __restrict__ out) {
    __shared__ float srow[TF];
    __shared__ float red[16];
    __shared__ float bc[1];

    int row = blockIdx.x;                   // b*NB + n
    int n = row % NB;
    int tid = threadIdx.x;                  // 512
    const float* bandrow = g_band + (size_t)row * TF2;
    const float* vnrrow  = out + FEAT_ELEMS + (size_t)row * TF;
    float*       featrow = out + (size_t)row * TF;

    const float invTF = 1.0f / (float)TF;

    float s = 0.0f;
    for (int t = tid; t < TF; t += 512) { float v = bandrow[t]; srow[t] = v; s += v; }
    s = block_reduce_sum512(s, red);
    float mu = s * invTF;

    float s2 = 0.0f, s4 = 0.0f;
    for (int t = tid; t < TF; t += 512) {
        float d = srow[t] - mu;
        float d2 = d * d;
        s2 += d2;
        s4 += d2 * d2;
    }
    s2 = block_reduce_sum512(s2, red);
    s4 = block_reduce_sum512(s4, red);

    if (tid == 0) {
        float var  = fmaxf(s2 * invTF, 1e-8f);
        float kurt = (s4 * invTF) / (fmaf(var, var, 1e-8f));
        float kn   = (kurt - 3.0f) * (1.0f / 3.0f);
        float gate = 1.0f / (1.0f + expf(-(gw_p[n] * kn + gb_p[n])));
        float fl   = 1.0f / (1.0f + expf(-gf_p[n]));
        bc[0] = gate * (1.0f - fl) + fl;
    }
    __syncthreads();
    float g0 = bc[0];

    float sg = 0.0f;
    for (int t = tid; t < TF; t += 512) {
        float g = srow[t] * g0 * fmaf(0.5f, vnrrow[t], 0.5f);
        srow[t] = g;
        sg += g;
    }
    sg = block_reduce_sum512(sg, red);
    float mu2 = sg * invTF;

    float sv = 0.0f;
    for (int t = tid; t < TF; t += 512) {
        float d = srow[t] - mu2;
        sv += d * d;
    }
    sv = block_reduce_sum512(sv, red);
    float inv = rsqrtf(sv * invTF + 1e-5f);

    for (int t = tid; t < TF; t += 512)
        featrow[t] = (srow[t] - mu2) * inv;
}

// ---------------- launcher ----------------
extern "C" void kernel_launch(void* const* d_in, const int* in_sizes, int n_in,
                              void* d_out, int out_size) {
    const float* vibration   = (const float*)d_in[0];
    const float* freq_fb     = (const float*)d_in[1];
    const float* window      = (const float*)d_in[2];
    const float* noise_scale = (const float*)d_in[3];
    const float* raw_rise    = (const float*)d_in[4];
    const float* raw_fall    = (const float*)d_in[5];
    const float* gate_weight = (const float*)d_in[6];
    const float* gate_bias   = (const float*)d_in[7];
    const float* gate_floor  = (const float*)d_in[8];
    float* out = (float*)d_out;

    init_twiddles<<<1, 512>>>();
    init_csr<<<1, 64>>>(freq_fb);
    stft16_kernel<<<BATCH * NTB, 256>>>(vibration, window);
    noise_band_kernel<<<BATCH * 16, NBT>>>(raw_rise, raw_fall, noise_scale, out);
    gate_kernel<<<BATCH * NB, 512>>>(gate_weight, gate_bias, gate_floor, out);
}

// round 16
// speedup vs baseline: 1.0779x; 1.0779x over previous
#include <cuda_runtime.h>
#include <cuda_pipeline.h>
#include <math.h>

#define NFFT   512
#define NFREQ  257
#define HOP    64
#define BATCH  32
#define TLEN   256000
#define TF     4001
#define TF2    4096                 // padded band row stride
#define TB2    4096                 // padded t rows per batch (mag)
#define FP     268                  // mag f-row stride (floats), 16B-aligned
#define NB     40
#define NFRAMES (BATCH*TF)
#define NTB     251                 // 16-frame tiles per batch
#define FEAT_ELEMS ((size_t)BATCH*NB*TF)

// segmented speculative scan params (aligned grid)
#define SEGL   256
#define WARM   192                  // contraction (1-fall)^192 ~ 9e-5
#define TC     8                    // t per chunk
#define WCHK   (WARM/TC)            // 24 warm chunks
#define SCHK   (SEGL/TC)            // 32 write chunks

// ---------------- scratch (no cudaMalloc allowed; zero-initialized) ----------
__device__ float g_tw_re[512];
__device__ float g_tw_im[512];
__device__ float g_mag [(size_t)BATCH * TB2 * FP];   // (b,t,f) natural, padded
__device__ float g_band[(size_t)BATCH * NB * TF2];   // (b,n,t) padded
__device__ int   g_lo [NB];
__device__ int   g_off[NB + 1];
__device__ float g_w  [768];        // CSR weights, nnz <= 514

// ---------------- init: twiddles + CSR of triangular fb ----------------
__global__ void init_twiddles() {
    int k = threadIdx.x;            // 512 threads
    double ang = -2.0 * M_PI * (double)k / (double)NFFT;
    g_tw_re[k] = (float)cos(ang);
    g_tw_im[k] = (float)sin(ang);
}

// fb rows are contiguous nonzero runs [lo, hi); build CSR (lo, off, w).
__global__ void init_csr(const float* __restrict__ fb) {
    __shared__ int s_len[NB];
    int n = threadIdx.x;            // 64 threads
    if (n < NB) {
        int lo = NFREQ, hi = 0;
        for (int f = 0; f < NFREQ; ++f) {
            if (fb[n * NFREQ + f] != 0.0f) { if (f < lo) lo = f; hi = f + 1; }
        }
        if (hi <= lo) { lo = 0; hi = 0; }
        g_lo[n] = lo;
        s_len[n] = hi - lo;
    }
    __syncthreads();
    if (n == 0) {
        int off = 0;
        for (int i = 0; i < NB; ++i) { g_off[i] = off; off += s_len[i]; }
        g_off[NB] = off;
    }
    __syncthreads();
    if (n < NB) {
        int o = g_off[n], lo = g_lo[n], len = s_len[n];
        for (int i = 0; i < len; ++i) g_w[o + i] = fb[n * NFREQ + lo + i];
    }
}

// ---------------- complex helpers ----------------
__device__ __forceinline__ float2 cadd(float2 a, float2 b) { return make_float2(a.x+b.x, a.y+b.y); }
__device__ __forceinline__ float2 csub(float2 a, float2 b) { return make_float2(a.x-b.x, a.y-b.y); }
__device__ __forceinline__ float2 cmul(float2 a, float2 w) {
    return make_float2(fmaf(a.x, w.x, -a.y*w.y), fmaf(a.x, w.y, a.y*w.x));
}

// 8-point DFT
__device__ __forceinline__ void dft8(const float2* v, float2* y) {
    float2 e0s = cadd(v[0], v[4]), e0d = csub(v[0], v[4]);
    float2 e1s = cadd(v[2], v[6]), e1d = csub(v[2], v[6]);
    float2 o0s = cadd(v[1], v[5]), o0d = csub(v[1], v[5]);
    float2 o1s = cadd(v[3], v[7]), o1d = csub(v[3], v[7]);
    float2 E0 = cadd(e0s, e1s);
    float2 E2 = csub(e0s, e1s);
    float2 E1 = make_float2(e0d.x + e1d.y, e0d.y - e1d.x);
    float2 E3 = make_float2(e0d.x - e1d.y, e0d.y + e1d.x);
    float2 O0 = cadd(o0s, o1s);
    float2 O2 = csub(o0s, o1s);
    float2 O1 = make_float2(o0d.x + o1d.y, o0d.y - o1d.x);
    float2 O3 = make_float2(o0d.x - o1d.y, o0d.y + o1d.x);
    const float C = 0.70710678118654752440f;
    float2 t1 = make_float2(C*(O1.x + O1.y), C*(O1.y - O1.x));
    float2 t2 = make_float2(O2.y, -O2.x);
    float2 t3 = make_float2(C*(O3.y - O3.x), -C*(O3.x + O3.y));
    y[0] = cadd(E0, O0);  y[4] = csub(E0, O0);
    y[1] = cadd(E1, t1);  y[5] = csub(E1, t1);
    y[2] = cadd(E2, t2);  y[6] = csub(E2, t2);
    y[3] = cadd(E3, t3);  y[7] = csub(E3, t3);
}

// ---------------- K1: STFT magnitude -> natural (b,t,f) rows ----------------
__global__ void __launch_bounds__(256)
stft16_kernel(const float* __restrict__ x, const float* __restrict__ win) {
    __shared__ float buf_re[4][576], buf_im[4][576];
    __shared__ float magt[16][258];
    __shared__ float2 s_tw[512];

    int tid = threadIdx.x;
    int b  = blockIdx.x / NTB;
    int tb = blockIdx.x - b * NTB;
    int t0 = tb * 16;
    const float* xb = x + (size_t)b * TLEN;

    for (int i = tid; i < 512; i += 256)
        s_tw[i] = make_float2(g_tw_re[i], g_tw_im[i]);
    __syncthreads();

    int tile = tid >> 6;
    int j    = tid & 63;
    int mB = j >> 3, jp = j & 7;
    int mC = j & 7,  m2C = j >> 3;

    for (int half = 0; half < 2; ++half) {
        int pl  = half * 4 + tile;            // pair-local 0..7
        int tA = t0 + 2 * pl, tB = tA + 1;    // frame times

        float2 a[8], y[8];
        #pragma unroll
        for (int l = 0; l < 8; ++l) {
            int n = j + 64 * l;
            float w = win[n];
            int i0 = tA * HOP + n - 256;
            if (i0 < 0) i0 = -i0; else if (i0 >= TLEN) i0 = 2 * TLEN - 2 - i0;
            int i1 = tB * HOP + n - 256;
            if (i1 < 0) i1 = -i1; else if (i1 >= TLEN) i1 = 2 * TLEN - 2 - i1;
            a[l] = make_float2(xb[i0] * w, xb[i1] * w);
        }

        dft8(a, y);
        #pragma unroll
        for (int m = 0; m < 8; ++m) {
            float2 c = (m == 0) ? y[0] : cmul(y[m], s_tw[j * m]);
            int idx = m * 64 + (j ^ (m << 3));
            buf_re[tile][idx] = c.x;
            buf_im[tile][idx] = c.y;
        }
        __syncthreads();

        #pragma unroll
        for (int l2 = 0; l2 < 8; ++l2) {
            int src = jp + 8 * l2;
            int idx = mB * 64 + (src ^ (mB << 3));
            a[l2] = make_float2(buf_re[tile][idx], buf_im[tile][idx]);
        }
        __syncthreads();
        dft8(a, y);
        #pragma unroll
        for (int m2 = 0; m2 < 8; ++m2) {
            float2 e = (m2 == 0) ? y[0] : cmul(y[m2], s_tw[8 * jp * m2]);
            int idx = m2 * 72 + mB * 9 + jp;
            buf_re[tile][idx] = e.x;
            buf_im[tile][idx] = e.y;
        }
        __syncthreads();

        #pragma unroll
        for (int q = 0; q < 8; ++q) {
            int idx = m2C * 72 + mC * 9 + q;
            a[q] = make_float2(buf_re[tile][idx], buf_im[tile][idx]);
        }
        __syncthreads();
        dft8(a, y);
        #pragma unroll
        for (int k2 = 0; k2 < 8; ++k2) {
            int k = 64 * k2 + j;
            buf_re[tile][k] = y[k2].x;
            buf_im[tile][k] = y[k2].y;
        }
        __syncthreads();

        int jlA = 2 * pl, jlB = jlA + 1;
        #pragma unroll
        for (int q = 0; q < 4; ++q) {
            int k  = j + 64 * q;
            int k2 = (NFFT - k) & (NFFT - 1);
            float xr = buf_re[tile][k],  xi = buf_im[tile][k];
            float yr = buf_re[tile][k2], yi = buf_im[tile][k2];
            float ar = 0.5f * (xr + yr);
            float ai = 0.5f * (xi - yi);
            float br = 0.5f * (xi + yi);
            float bi = 0.5f * (yr - xr);
            magt[jlA][k] = sqrtf(ar * ar + ai * ai);
            magt[jlB][k] = sqrtf(br * br + bi * bi);
        }
        if (j == 0) {
            float xr = buf_re[tile][256], xi = buf_im[tile][256];
            magt[jlA][256] = fabsf(xr);
            magt[jlB][256] = fabsf(xi);
        }
        __syncthreads();
    }

    // natural-row write-out: 16 coalesced 1028B rows
    for (int fr = 0; fr < 16; ++fr) {
        int t = t0 + fr;
        if (t < TF) {
            float* dst = g_mag + ((size_t)b * TB2 + t) * FP;
            for (int f = tid; f < NFREQ; f += 256)
                dst[f] = magt[fr][f];
        }
    }
}

// ---------------- K2: FUSED noise scan + VNR + band reduction (round-13) -----
__global__ void __launch_bounds__(288)
noise_band_kernel(const float* __restrict__ raw_rise,
                  const float* __restrict__ raw_fall,
                  const float* __restrict__ noise_scale_p,
                  float* __restrict__ out) {
    __shared__ __align__(16) float mtile[2][TC * FP];  // 17.2 KB
    __shared__ __align__(16) float vtile[TC * FP];     //  8.6 KB
    __shared__ float s_w[768];
    __shared__ int   s_off[NB + 1];
    __shared__ int   s_lo [NB];

    int tid = threadIdx.x;            // 288 = 9 warps
    int b = blockIdx.x >> 4;
    int s = blockIdx.x & 15;

    for (int i = tid; i < 768; i += 288) s_w[i] = g_w[i];
    if (tid <= NB) s_off[tid] = g_off[tid];
    if (tid < NB)  s_lo[tid]  = g_lo[tid];

    float rise  = 1.0f / (1.0f + expf(-raw_rise[0]));
    float fall  = 1.0f / (1.0f + expf(-raw_fall[0]));
    float scale = fabsf(noise_scale_p[0]);
    float* out_vnr = out + FEAT_ELEMS;

    int f = tid;
    bool act = (f < NFREQ);
    size_t magb = (size_t)b * TB2;

    // floor = 0.5 * max(min over t<20, 1e-5); coalesced rows
    float mn = 3.4e38f;
    if (act) {
        #pragma unroll 4
        for (int t = 0; t < 20; ++t)
            mn = fminf(mn, g_mag[(magb + t) * FP + f]);
    }
    mn = fmaxf(mn, 1e-5f);
    float floorv = 0.5f * mn;
    float nf = mn;                    // exact init (s==0)

    int t0 = s * SEGL;
    int tstart = s ? (t0 - WARM) : 0;
    int wch = s ? WCHK : 0;
    int nch = wch + SCHK;

    // prime chunk 0
    {
        const float* src = g_mag + (magb + tstart) * FP;
        for (int i = tid; i < TC * 67; i += 288) {
            int row = i / 67, c = i - row * 67;
            __pipeline_memcpy_async(&mtile[0][row * FP + c * 4],
                                    src + (size_t)row * FP + c * 4, 16);
        }
        __pipeline_commit();
    }

    for (int ch = 0; ch < nch; ++ch) {
        int cur = ch & 1;
        __pipeline_wait_prior(0);
        __syncthreads();              // mtile[cur] ready; prev phase2 done

        if (ch + 1 < nch) {           // prefetch next chunk
            const float* src = g_mag + (magb + tstart + (ch + 1) * TC) * FP;
            float* dst = mtile[cur ^ 1];
            for (int i = tid; i < TC * 67; i += 288) {
                int row = i / 67, c = i - row * 67;
                __pipeline_memcpy_async(&dst[row * FP + c * 4],
                                        src + (size_t)row * FP + c * 4, 16);
            }
            __pipeline_commit();
        }

        bool wr = (ch >= wch);
        if (act) {
            if (ch == 0 && s) nf = fmaxf(mtile[cur][f], floorv);  // spec init
            #pragma unroll
            for (int i = 0; i < TC; ++i) {
                float m = mtile[cur][i * FP + f];
                float d = m - nf;
                float a = (d > 0.0f) ? rise : fall;
                nf = fmaxf(fmaf(a, d, nf), floorv);
                if (wr) vtile[i * FP + f] = __fdividef(m, fmaf(scale, nf, 1e-8f));
            }
        }

        if (wr) {
            __syncthreads();          // vtile ready
            int tbase = tstart + ch * TC;
            for (int task = tid; task < NB * TC; task += 288) {
                int n  = task >> 3;
                int tl = task & 7;
                int tg = tbase + tl;
                if (tg < TF) {
                    int o0 = s_off[n], o1 = s_off[n + 1];
                    int lo = s_lo[n];
                    float sb = 0.0f, sv = 0.0f;
                    for (int o = o0; o < o1; ++o) {
                        int ff = lo + (o - o0);
                        float w = s_w[o];
                        sb = fmaf(w, mtile[cur][tl * FP + ff], sb);
                        sv = fmaf(w, vtile[tl * FP + ff], sv);
                    }
                    g_band[((size_t)b * NB + n) * TF2 + tg] = sb;
                    out_vnr[((size_t)b * NB + n) * TF + tg] = tanhf(sv * 0.1f);
                }
            }
        }
    }
}

// ---------------- K3: kurtosis gate + standardize, 3-pass raw moments --------
__device__ __forceinline__ float block_reduce_sum512(float v, float* red) {
    #pragma unroll
    for (int o = 16; o; o >>= 1) v += __shfl_xor_sync(0xffffffffu, v, o);
    int w = threadIdx.x >> 5, l = threadIdx.x & 31;
    __syncthreads();
    if (l == 0) red[w] = v;
    __syncthreads();
    float r = (l < 16) ? red[l] : 0.0f;
    if (w == 0) {
        #pragma unroll
        for (int o = 8; o; o >>= 1) r += __shfl_xor_sync(0xffffffffu, r, o);
        if (l == 0) red[0] = r;
    }
    __syncthreads();
    return red[0];
}

__global__ void __launch_bounds__(512)
gate_kernel(const float* __restrict__ gw_p,
            const float* __restrict__ gb_p,
            const float* __restrict__ gf_p,
            float* __restrict__ out) {
    __shared__ float srow[TF];
    __shared__ float red[16];
    __shared__ float bc[1];

    int row = blockIdx.x;                   // b*NB + n
    int n = row % NB;
    int tid = threadIdx.x;                  // 512
    const float* bandrow = g_band + (size_t)row * TF2;
    const float* vnrrow  = out + FEAT_ELEMS + (size_t)row * TF;
    float*       featrow = out + (size_t)row * TF;

    const float invTF = 1.0f / (float)TF;

    // pass 1: raw moments s1..s4 while caching the row
    float s1 = 0.0f, s2 = 0.0f, s3 = 0.0f, s4 = 0.0f;
    for (int t = tid; t < TF; t += 512) {
        float v = bandrow[t];
        srow[t] = v;
        float v2 = v * v;
        s1 += v;  s2 += v2;
        s3 += v2 * v;  s4 += v2 * v2;
    }
    s1 = block_reduce_sum512(s1, red);
    s2 = block_reduce_sum512(s2, red);
    s3 = block_reduce_sum512(s3, red);
    s4 = block_reduce_sum512(s4, red);

    if (tid == 0) {
        float mu  = s1 * invTF;
        float m2r = s2 * invTF;
        float m3r = s3 * invTF;
        float m4r = s4 * invTF;
        float mu2 = mu * mu;
        float var = fmaxf(m2r - mu2, 1e-8f);
        float m4c = m4r - 4.0f * mu * m3r + 6.0f * mu2 * m2r - 3.0f * mu2 * mu2;
        float kurt = m4c / (fmaf(var, var, 1e-8f));
        float kn   = (kurt - 3.0f) * (1.0f / 3.0f);
        float gate = 1.0f / (1.0f + expf(-(gw_p[n] * kn + gb_p[n])));
        float fl   = 1.0f / (1.0f + expf(-gf_p[n]));
        bc[0] = gate * (1.0f - fl) + fl;
    }
    __syncthreads();
    float g0 = bc[0];

    // pass 2: apply gate; accumulate mean + raw second moment of gated
    float sg = 0.0f, sg2 = 0.0f;
    for (int t = tid; t < TF; t += 512) {
        float g = srow[t] * g0 * fmaf(0.5f, vnrrow[t], 0.5f);
        srow[t] = g;
        sg  += g;
        sg2 += g * g;
    }
    sg  = block_reduce_sum512(sg, red);
    sg2 = block_reduce_sum512(sg2, red);
    float mug  = sg * invTF;
    float varg = fmaxf(sg2 * invTF - mug * mug, 0.0f);
    float inv  = rsqrtf(varg + 1e-5f);

    // pass 3: standardize + write
    for (int t = tid; t < TF; t += 512)
        featrow[t] = (srow[t] - mug) * inv;
}

// ---------------- launcher ----------------
extern "C" void kernel_launch(void* const* d_in, const int* in_sizes, int n_in,
                              void* d_out, int out_size) {
    const float* vibration   = (const float*)d_in[0];
    const float* freq_fb     = (const float*)d_in[1];
    const float* window      = (const float*)d_in[2];
    const float* noise_scale = (const float*)d_in[3];
    const float* raw_rise    = (const float*)d_in[4];
    const float* raw_fall    = (const float*)d_in[5];
    const float* gate_weight = (const float*)d_in[6];
    const float* gate_bias   = (const float*)d_in[7];
    const float* gate_floor  = (const float*)d_in[8];
    float* out = (float*)d_out;

    init_twiddles<<<1, 512>>>();
    init_csr<<<1, 64>>>(freq_fb);
    stft16_kernel<<<BATCH * NTB, 256>>>(vibration, window);
    noise_band_kernel<<<BATCH * 16, 288>>>(raw_rise, raw_fall, noise_scale, out);
    gate_kernel<<<BATCH * NB, 512>>>(gate_weight, gate_bias, gate_floor, out);
}